// round 2
// baseline (speedup 1.0000x reference)
#include <cuda_runtime.h>
#include <math.h>

#define BB 2
#define CY 96
#define CS 48
#define NN 4096
#define SCALE 0.14433756729740643f  /* 48^-0.5 */

// ---------------- scratch (device globals: no runtime allocation) ----------
__device__ float g_Spe[BB*CS*NN];
__device__ float g_Ype[BB*CY*NN];
__device__ float g_Y1 [BB*NN*CS];
__device__ float g_Q  [BB*NN*CS];
__device__ float g_K  [BB*NN*CS];
__device__ float g_V  [BB*NN*CS];
__device__ float g_X  [BB*NN*CS];
__device__ float g_Y3 [BB*CY*NN];
__device__ float g_m  [BB*NN];
__device__ float g_iz [BB*NN];
__device__ float g_Lt [(size_t)BB*NN*NN];   // 128 MB: logits transposed [b][k][q]

// ---------------- positional encoding + add --------------------------------
// pe[ch, d, h, w]:  c = C/3 (exact here). blk = ch/c, t = ch%c.
//   blk 0,1 -> emb(h)[t]   (faithful torch broadcasting quirk: both x and y
//   blocks read the *h* index since x==y==16)
//   blk 2   -> emb(w)[t]
//   emb(n)[t] = t < c/2 ? sin(n*10000^{-2t/c}) : cos(n*10000^{-2(t-c/2)/c})
__device__ __forceinline__ float pe_val(int ch, int h, int w, int c) {
    int blk = ch / c, t = ch - blk * c;
    int pos = (blk < 2) ? h : w;
    int half = c >> 1;
    float val;
    if (t < half) {
        float invf = powf(10000.f, -2.f * (float)t / (float)c);
        val = sinf((float)pos * invf);
    } else {
        float invf = powf(10000.f, -2.f * (float)(t - half) / (float)c);
        val = cosf((float)pos * invf);
    }
    return val;
}

__global__ void k_addpe_s(const float* __restrict__ S) {
    int i = blockIdx.x * blockDim.x + threadIdx.x;
    if (i >= BB * CS * NN) return;
    int n = i & (NN - 1);
    int ch = (i >> 12) % CS;
    int h = (n >> 4) & 15, w = n & 15;
    g_Spe[i] = S[i] + pe_val(ch, h, w, 16);
}

__global__ void k_addpe_y(const float* __restrict__ Y) {
    int i = blockIdx.x * blockDim.x + threadIdx.x;
    if (i >= BB * CY * NN) return;
    int n = i & (NN - 1);
    int ch = (i >> 12) % CY;
    int h = (n >> 4) & 15, w = n & 15;
    g_Ype[i] = Y[i] + pe_val(ch, h, w, 32);
}

// ---------------- S1 projection fused with V = S1 @ Wv ---------------------
// block: (n-tile of 64, b). 256 threads. thread -> (n = t&63, eg = t>>6),
// each handles 12 output channels.
__global__ __launch_bounds__(256) void k_proj_sv(
    const float* __restrict__ w_s, const float* __restrict__ b_s,
    const float* __restrict__ g_s, const float* __restrict__ be_s,
    const float* __restrict__ Wv)
{
    __shared__ float in_s[CS * 64];         // [c][n]
    __shared__ float wt[CS * CS];           // wt[c*48+e] = w_s[e*48+c]
    __shared__ float wv[CS * CS];           // natural [d][e]
    __shared__ float s1[64 * 49];           // [n][d], pad 49

    int b = blockIdx.y, n0 = blockIdx.x * 64, t = threadIdx.x;
    for (int i = t; i < CS * CS; i += 256) {
        int e = i % CS, c = i / CS;
        wt[i] = w_s[e * CS + c];
        wv[i] = Wv[i];
    }
    const float* src = g_Spe + (b * CS) * NN + n0;
    for (int i = t; i < CS * 64; i += 256) {
        int c = i >> 6, n = i & 63;
        in_s[i] = src[c * NN + n];
    }
    __syncthreads();

    int n = t & 63, eg = t >> 6;
    float acc[12];
#pragma unroll
    for (int j = 0; j < 12; j++) acc[j] = 0.f;
    for (int c = 0; c < CS; c++) {
        float x = in_s[c * 64 + n];
#pragma unroll
        for (int v = 0; v < 3; v++) {
            float4 w4 = *(const float4*)&wt[c * CS + eg * 12 + v * 4];
            acc[v*4+0] += w4.x * x; acc[v*4+1] += w4.y * x;
            acc[v*4+2] += w4.z * x; acc[v*4+3] += w4.w * x;
        }
    }
    float inv = rsqrtf(1.f + 1e-5f);
#pragma unroll
    for (int j = 0; j < 12; j++) {
        int e = eg * 12 + j;
        float y = (acc[j] + b_s[e]) * (g_s[e] * inv) + be_s[e];
        s1[n * 49 + e] = fmaxf(y, 0.f);
    }
    __syncthreads();

#pragma unroll
    for (int j = 0; j < 12; j++) acc[j] = 0.f;
    for (int d = 0; d < CS; d++) {
        float x = s1[n * 49 + d];
#pragma unroll
        for (int v = 0; v < 3; v++) {
            float4 w4 = *(const float4*)&wv[d * CS + eg * 12 + v * 4];
            acc[v*4+0] += w4.x * x; acc[v*4+1] += w4.y * x;
            acc[v*4+2] += w4.z * x; acc[v*4+3] += w4.w * x;
        }
    }
    float* dst = g_V + ((b * NN + n0 + n) * CS) + eg * 12;
#pragma unroll
    for (int v = 0; v < 3; v++)
        *(float4*)&dst[v * 4] = make_float4(acc[v*4], acc[v*4+1], acc[v*4+2], acc[v*4+3]);
}

// ---------------- Y1 projection (96 -> 48) ---------------------------------
__global__ __launch_bounds__(256) void k_proj_y1(
    const float* __restrict__ w_y, const float* __restrict__ b_y,
    const float* __restrict__ g_y, const float* __restrict__ be_y)
{
    __shared__ float in_s[CY * 64];     // [c][n]
    __shared__ float wt[CY * CS];       // wt[c*48+e] = w_y[e*96+c]

    int b = blockIdx.y, n0 = blockIdx.x * 64, t = threadIdx.x;
    for (int i = t; i < CY * CS; i += 256) {
        int e = i % CS, c = i / CS;
        wt[i] = w_y[e * CY + c];
    }
    const float* src = g_Ype + (b * CY) * NN + n0;
    for (int i = t; i < CY * 64; i += 256) {
        int c = i >> 6, n = i & 63;
        in_s[i] = src[c * NN + n];
    }
    __syncthreads();

    int n = t & 63, eg = t >> 6;
    float acc[12];
#pragma unroll
    for (int j = 0; j < 12; j++) acc[j] = 0.f;
    for (int c = 0; c < CY; c++) {
        float x = in_s[c * 64 + n];
#pragma unroll
        for (int v = 0; v < 3; v++) {
            float4 w4 = *(const float4*)&wt[c * CS + eg * 12 + v * 4];
            acc[v*4+0] += w4.x * x; acc[v*4+1] += w4.y * x;
            acc[v*4+2] += w4.z * x; acc[v*4+3] += w4.w * x;
        }
    }
    float inv = rsqrtf(1.f + 1e-5f);
    float* dst = g_Y1 + ((b * NN + n0 + n) * CS) + eg * 12;
#pragma unroll
    for (int j = 0; j < 12; j++) {
        int e = eg * 12 + j;
        float y = (acc[j] + b_y[e]) * (g_y[e] * inv) + be_y[e];
        dst[j] = fmaxf(y, 0.f);
    }
}

// ---------------- Q = Y1 @ Wq, K = Y1 @ Wk ---------------------------------
__global__ __launch_bounds__(256) void k_qk(
    const float* __restrict__ Wq, const float* __restrict__ Wk)
{
    __shared__ float y1[64 * 49];       // [n][d]
    __shared__ float wq[CS * CS];       // natural [d][e]
    __shared__ float wk[CS * CS];

    int b = blockIdx.y, n0 = blockIdx.x * 64, t = threadIdx.x;
    for (int i = t; i < CS * CS; i += 256) { wq[i] = Wq[i]; wk[i] = Wk[i]; }
    const float* src = g_Y1 + (b * NN + n0) * CS;
    for (int i = t; i < 64 * CS; i += 256) {
        int n = i / CS, d = i % CS;
        y1[n * 49 + d] = src[i];
    }
    __syncthreads();

    int n = t & 63, eg = t >> 6;
    float aq[12], ak[12];
#pragma unroll
    for (int j = 0; j < 12; j++) { aq[j] = 0.f; ak[j] = 0.f; }
    for (int d = 0; d < CS; d++) {
        float x = y1[n * 49 + d];
#pragma unroll
        for (int v = 0; v < 3; v++) {
            float4 q4 = *(const float4*)&wq[d * CS + eg * 12 + v * 4];
            float4 k4 = *(const float4*)&wk[d * CS + eg * 12 + v * 4];
            aq[v*4+0] += q4.x * x; aq[v*4+1] += q4.y * x;
            aq[v*4+2] += q4.z * x; aq[v*4+3] += q4.w * x;
            ak[v*4+0] += k4.x * x; ak[v*4+1] += k4.y * x;
            ak[v*4+2] += k4.z * x; ak[v*4+3] += k4.w * x;
        }
    }
    float* dq = g_Q + ((b * NN + n0 + n) * CS) + eg * 12;
    float* dk = g_K + ((b * NN + n0 + n) * CS) + eg * 12;
#pragma unroll
    for (int v = 0; v < 3; v++) {
        *(float4*)&dq[v * 4] = make_float4(aq[v*4], aq[v*4+1], aq[v*4+2], aq[v*4+3]);
        *(float4*)&dk[v * 4] = make_float4(ak[v*4], ak[v*4+1], ak[v*4+2], ak[v*4+3]);
    }
}

// ---------------- logits: Lt[b][k][q] = SCALE * Q[q]·K[k] ------------------
// 64x64 output tile, 256 threads, 4x4 micro-tile, d=48 inner.
__global__ __launch_bounds__(256) void k_logits() {
    __shared__ float Qs[CS * 64];   // [d][q]
    __shared__ float Ks[CS * 64];   // [d][k]

    int q0 = blockIdx.x * 64, k0 = blockIdx.y * 64, b = blockIdx.z;
    int t = threadIdx.x;
    {
        int n = t & 63, v = t >> 6;
        const float* sq = g_Q + ((b * NN + q0 + n) * CS);
        const float* sk = g_K + ((b * NN + k0 + n) * CS);
#pragma unroll
        for (int r = 0; r < 3; r++) {
            int dv = v + r * 4;
            float4 x = *(const float4*)&sq[dv * 4];
            Qs[(dv*4+0)*64+n] = x.x; Qs[(dv*4+1)*64+n] = x.y;
            Qs[(dv*4+2)*64+n] = x.z; Qs[(dv*4+3)*64+n] = x.w;
            float4 y = *(const float4*)&sk[dv * 4];
            Ks[(dv*4+0)*64+n] = y.x; Ks[(dv*4+1)*64+n] = y.y;
            Ks[(dv*4+2)*64+n] = y.z; Ks[(dv*4+3)*64+n] = y.w;
        }
    }
    __syncthreads();

    int tq = t & 15, tk = t >> 4;
    float acc[4][4];
#pragma unroll
    for (int i = 0; i < 4; i++)
#pragma unroll
        for (int j = 0; j < 4; j++) acc[i][j] = 0.f;

    for (int d = 0; d < CS; d++) {
        float4 kk = *(const float4*)&Ks[d * 64 + tk * 4];
        float4 qq = *(const float4*)&Qs[d * 64 + tq * 4];
        float ka[4] = {kk.x, kk.y, kk.z, kk.w};
        float qa[4] = {qq.x, qq.y, qq.z, qq.w};
#pragma unroll
        for (int i = 0; i < 4; i++)
#pragma unroll
            for (int j = 0; j < 4; j++) acc[i][j] += ka[i] * qa[j];
    }
#pragma unroll
    for (int i = 0; i < 4; i++) {
        size_t row = (size_t)(b * NN + k0 + tk * 4 + i) * NN + q0 + tq * 4;
        *(float4*)&g_Lt[row] = make_float4(acc[i][0]*SCALE, acc[i][1]*SCALE,
                                           acc[i][2]*SCALE, acc[i][3]*SCALE);
    }
}

// ---------------- column stats: online max & sumexp over q -----------------
__global__ __launch_bounds__(256) void k_colstats() {
    int k = blockIdx.x, b = blockIdx.y;
    const float* row = g_Lt + (size_t)(b * NN + k) * NN;
    float m = -1e30f, s = 0.f;
    for (int q = threadIdx.x; q < NN; q += 256) {
        float v = row[q];
        if (v > m) { s = s * __expf(m - v) + 1.f; m = v; }
        else       { s += __expf(v - m); }
    }
#pragma unroll
    for (int o = 16; o; o >>= 1) {
        float m2 = __shfl_xor_sync(0xffffffffu, m, o);
        float s2 = __shfl_xor_sync(0xffffffffu, s, o);
        float M = fmaxf(m, m2);
        s = s * __expf(m - M) + s2 * __expf(m2 - M);
        m = M;
    }
    __shared__ float sm[8], ss[8];
    int w = threadIdx.x >> 5, l = threadIdx.x & 31;
    if (l == 0) { sm[w] = m; ss[w] = s; }
    __syncthreads();
    if (threadIdx.x == 0) {
        float M = sm[0], Ssum = ss[0];
#pragma unroll
        for (int i = 1; i < 8; i++) {
            float M2 = fmaxf(M, sm[i]);
            Ssum = Ssum * __expf(M - M2) + ss[i] * __expf(sm[i] - M2);
            M = M2;
        }
        g_m [b * NN + k] = M;
        g_iz[b * NN + k] = 1.f / Ssum;
    }
}

// ---------------- AV: x[q][d] = sum_k exp(Lt[k][q]-m[k])*izk * V[k][d] -----
__global__ __launch_bounds__(256) void k_av() {
    __shared__ float Ps[64 * 64];   // [k][q]
    __shared__ float Vs[64 * CS];   // [k][d]

    int q0 = blockIdx.x * 64, b = blockIdx.y, t = threadIdx.x;
    int tq = t & 15, td = t >> 4;
    float acc[4][3];
#pragma unroll
    for (int i = 0; i < 4; i++)
#pragma unroll
        for (int j = 0; j < 3; j++) acc[i][j] = 0.f;

    int kl = t >> 2, qb = (t & 3) * 16;
    for (int k0 = 0; k0 < NN; k0 += 64) {
        float mk = g_m [b * NN + k0 + kl];
        float zk = g_iz[b * NN + k0 + kl];
        const float* srcL = g_Lt + (size_t)(b * NN + k0 + kl) * NN + q0 + qb;
#pragma unroll
        for (int r = 0; r < 4; r++) {
            float4 x = *(const float4*)&srcL[r * 4];
            float* p = &Ps[kl * 64 + qb + r * 4];
            p[0] = __expf(x.x - mk) * zk; p[1] = __expf(x.y - mk) * zk;
            p[2] = __expf(x.z - mk) * zk; p[3] = __expf(x.w - mk) * zk;
        }
        const float* srcV = g_V + ((b * NN + k0 + kl) * CS) + (t & 3) * 12;
        float* dv = &Vs[kl * CS + (t & 3) * 12];
#pragma unroll
        for (int r = 0; r < 3; r++)
            *(float4*)&dv[r * 4] = *(const float4*)&srcV[r * 4];
        __syncthreads();

        for (int kk = 0; kk < 64; kk++) {
            float4 p = *(const float4*)&Ps[kk * 64 + tq * 4];
            float v0 = Vs[kk * CS + td * 3 + 0];
            float v1 = Vs[kk * CS + td * 3 + 1];
            float v2 = Vs[kk * CS + td * 3 + 2];
            float pa[4] = {p.x, p.y, p.z, p.w};
#pragma unroll
            for (int i = 0; i < 4; i++) {
                acc[i][0] += pa[i] * v0;
                acc[i][1] += pa[i] * v1;
                acc[i][2] += pa[i] * v2;
            }
        }
        __syncthreads();
    }
#pragma unroll
    for (int i = 0; i < 4; i++) {
        float* dst = g_X + ((b * NN + q0 + tq * 4 + i) * CS) + td * 3;
        dst[0] = acc[i][0]; dst[1] = acc[i][1]; dst[2] = acc[i][2];
    }
}

// ---------------- conv3d 3x3x3 (96 -> 96), SAME padding --------------------
// grid (cog=6, d=16, b=2), 256 threads = 16h x 16w, 16 co per thread.
__global__ __launch_bounds__(256) void k_conv3d(
    const float* __restrict__ w3, const float* __restrict__ b3)
{
    __shared__ __align__(16) float in_s[3 * 18 * 18];
    __shared__ __align__(16) float ws[27][16];      // [tap][co]

    int cog = blockIdx.x, d = blockIdx.y, b = blockIdx.z;
    int t = threadIdx.x, h = t >> 4, w = t & 15;

    float acc[16];
#pragma unroll
    for (int co = 0; co < 16; co++) acc[co] = b3[cog * 16 + co];

    for (int ci = 0; ci < CY; ci++) {
        const float* src = g_Ype + (b * CY + ci) * NN;
        for (int i = t; i < 3 * 324; i += 256) {
            int dd = i / 324, rem = i - dd * 324, r = rem / 18, c = rem - r * 18;
            int z = d + dd - 1, y = r - 1, x = c - 1;
            float v = 0.f;
            if (z >= 0 && z < 16 && y >= 0 && y < 16 && x >= 0 && x < 16)
                v = src[z * 256 + y * 16 + x];
            in_s[i] = v;
        }
        // FIX (R1): 432 weight slots but only 256 threads -> must stride.
        for (int i = t; i < 16 * 27; i += 256) {
            int tap = i % 27, co = i / 27;
            ws[tap][co] = w3[(cog * 16 + co) * (CY * 27) + ci * 27 + tap];
        }
        __syncthreads();

        float in_r[27];
#pragma unroll
        for (int dd = 0; dd < 3; dd++)
#pragma unroll
            for (int dy = 0; dy < 3; dy++)
#pragma unroll
                for (int dx = 0; dx < 3; dx++)
                    in_r[dd*9+dy*3+dx] = in_s[dd*324 + (h+dy)*18 + (w+dx)];

#pragma unroll
        for (int tap = 0; tap < 27; tap++) {
            float x = in_r[tap];
            float4 w0 = *(const float4*)&ws[tap][0];
            float4 w1 = *(const float4*)&ws[tap][4];
            float4 w2 = *(const float4*)&ws[tap][8];
            float4 w3v= *(const float4*)&ws[tap][12];
            acc[0]+=w0.x*x; acc[1]+=w0.y*x; acc[2]+=w0.z*x; acc[3]+=w0.w*x;
            acc[4]+=w1.x*x; acc[5]+=w1.y*x; acc[6]+=w1.z*x; acc[7]+=w1.w*x;
            acc[8]+=w2.x*x; acc[9]+=w2.y*x; acc[10]+=w2.z*x; acc[11]+=w2.w*x;
            acc[12]+=w3v.x*x; acc[13]+=w3v.y*x; acc[14]+=w3v.z*x; acc[15]+=w3v.w*x;
        }
        __syncthreads();
    }
    int n = d * 256 + t;
#pragma unroll
    for (int co = 0; co < 16; co++)
        g_Y3[(b * CY + cog * 16 + co) * NN + n] = acc[co];
}

// ---------------- Z output: bn_relu(X @ w_o) * Spe -> out[:, 0:48] ---------
__global__ __launch_bounds__(256) void k_zout(
    const float* __restrict__ w_o, const float* __restrict__ b_o,
    const float* __restrict__ g_o, const float* __restrict__ be_o,
    float* __restrict__ out)
{
    __shared__ float xs[CS * 64];   // [d][n]
    __shared__ float wot[CS * CS];  // wot[d*48+e] = w_o[e*48+d]

    int b = blockIdx.y, n0 = blockIdx.x * 64, t = threadIdx.x;
    for (int i = t; i < CS * CS; i += 256) {
        int e = i % CS, d = i / CS;
        wot[i] = w_o[e * CS + d];
    }
    {
        int n = t & 63, v = t >> 6;
        const float* src = g_X + ((b * NN + n0 + n) * CS);
#pragma unroll
        for (int r = 0; r < 3; r++) {
            int dv = v + r * 4;
            float4 x = *(const float4*)&src[dv * 4];
            xs[(dv*4+0)*64+n] = x.x; xs[(dv*4+1)*64+n] = x.y;
            xs[(dv*4+2)*64+n] = x.z; xs[(dv*4+3)*64+n] = x.w;
        }
    }
    __syncthreads();

    int n = t & 63, eg = t >> 6;
    float acc[12];
#pragma unroll
    for (int j = 0; j < 12; j++) acc[j] = 0.f;
    for (int d = 0; d < CS; d++) {
        float x = xs[d * 64 + n];
#pragma unroll
        for (int v = 0; v < 3; v++) {
            float4 w4 = *(const float4*)&wot[d * CS + eg * 12 + v * 4];
            acc[v*4+0] += w4.x * x; acc[v*4+1] += w4.y * x;
            acc[v*4+2] += w4.z * x; acc[v*4+3] += w4.w * x;
        }
    }
    float inv = rsqrtf(1.f + 1e-5f);
#pragma unroll
    for (int j = 0; j < 12; j++) {
        int e = eg * 12 + j;
        float y = (acc[j] + b_o[e]) * (g_o[e] * inv) + be_o[e];
        y = fmaxf(y, 0.f);
        float z = y * g_Spe[(b * CS + e) * NN + n0 + n];
        out[(b * 96 + e) * NN + n0 + n] = z;
    }
}

// ---------------- Y2 output: bn_relu(Y3 @ w_y2) -> out[:, 48:96] -----------
__global__ __launch_bounds__(256) void k_y2out(
    const float* __restrict__ w_y2, const float* __restrict__ b_y2,
    const float* __restrict__ g_y2, const float* __restrict__ be_y2,
    float* __restrict__ out)
{
    __shared__ float in_s[CY * 64];  // [c][n]
    __shared__ float wt[CY * CS];    // wt[c*48+e] = w_y2[e*96+c]

    int b = blockIdx.y, n0 = blockIdx.x * 64, t = threadIdx.x;
    for (int i = t; i < CY * CS; i += 256) {
        int e = i % CS, c = i / CS;
        wt[i] = w_y2[e * CY + c];
    }
    const float* src = g_Y3 + (b * CY) * NN + n0;
    for (int i = t; i < CY * 64; i += 256) {
        int c = i >> 6, n = i & 63;
        in_s[i] = src[c * NN + n];
    }
    __syncthreads();

    int n = t & 63, eg = t >> 6;
    float acc[12];
#pragma unroll
    for (int j = 0; j < 12; j++) acc[j] = 0.f;
    for (int c = 0; c < CY; c++) {
        float x = in_s[c * 64 + n];
#pragma unroll
        for (int v = 0; v < 3; v++) {
            float4 w4 = *(const float4*)&wt[c * CS + eg * 12 + v * 4];
            acc[v*4+0] += w4.x * x; acc[v*4+1] += w4.y * x;
            acc[v*4+2] += w4.z * x; acc[v*4+3] += w4.w * x;
        }
    }
    float inv = rsqrtf(1.f + 1e-5f);
#pragma unroll
    for (int j = 0; j < 12; j++) {
        int e = eg * 12 + j;
        float y = (acc[j] + b_y2[e]) * (g_y2[e] * inv) + be_y2[e];
        out[(b * 96 + 48 + e) * NN + n0 + n] = fmaxf(y, 0.f);
    }
}

// ---------------- launch ----------------------------------------------------
extern "C" void kernel_launch(void* const* d_in, const int* in_sizes, int n_in,
                              void* d_out, int out_size)
{
    const float* Y    = (const float*)d_in[0];
    const float* S    = (const float*)d_in[1];
    const float* w_s  = (const float*)d_in[2];
    const float* b_s  = (const float*)d_in[3];
    const float* g_s  = (const float*)d_in[4];
    const float* be_s = (const float*)d_in[5];
    const float* w_y  = (const float*)d_in[6];
    const float* b_y  = (const float*)d_in[7];
    const float* g_y  = (const float*)d_in[8];
    const float* be_y = (const float*)d_in[9];
    const float* Wq   = (const float*)d_in[10];
    const float* Wk   = (const float*)d_in[11];
    const float* Wv   = (const float*)d_in[12];
    const float* w_o  = (const float*)d_in[13];
    const float* b_o  = (const float*)d_in[14];
    const float* g_o  = (const float*)d_in[15];
    const float* be_o = (const float*)d_in[16];
    const float* w3   = (const float*)d_in[17];
    const float* b3   = (const float*)d_in[18];
    const float* w_y2 = (const float*)d_in[19];
    const float* b_y2 = (const float*)d_in[20];
    const float* g_y2 = (const float*)d_in[21];
    const float* be_y2= (const float*)d_in[22];
    float* out = (float*)d_out;

    k_addpe_s<<<(BB*CS*NN + 255)/256, 256>>>(S);
    k_addpe_y<<<(BB*CY*NN + 255)/256, 256>>>(Y);

    k_proj_sv<<<dim3(NN/64, BB), 256>>>(w_s, b_s, g_s, be_s, Wv);
    k_proj_y1<<<dim3(NN/64, BB), 256>>>(w_y, b_y, g_y, be_y);
    k_qk     <<<dim3(NN/64, BB), 256>>>(Wq, Wk);

    k_logits  <<<dim3(NN/64, NN/64, BB), 256>>>();
    k_colstats<<<dim3(NN, BB), 256>>>();
    k_av      <<<dim3(NN/64, BB), 256>>>();

    k_conv3d<<<dim3(CY/16, 16, BB), 256>>>(w3, b3);

    k_zout <<<dim3(NN/64, BB), 256>>>(w_o, b_o, g_o, be_o, out);
    k_y2out<<<dim3(NN/64, BB), 256>>>(w_y2, b_y2, g_y2, be_y2, out);
}